// round 11
// baseline (speedup 1.0000x reference)
#include <cuda_runtime.h>

#define BATCH 64
#define PIX   196
#define ENCD  2048
#define ATTD  512
#define DECD  512
#define EMBD  512
#define TT    32
#define NSTEP 31
#define VOC   30000
#define GATE_N 1536
#define MROWS (NSTEP * BATCH)   // 1984

// ---------------- device scratch ----------------
__device__ float g_att1[(size_t)BATCH * PIX * ATTD];     // 25.7 MB
__device__ float g_encw[(size_t)BATCH * PIX * GATE_N];   // 77 MB: enc @ W_ihc^T
__device__ float g_h[BATCH * DECD];
__device__ float g_gates[2 * BATCH * GATE_N];            // [0]=gi(full), [1]=gh(accum)
__device__ float g_att2[BATCH * ATTD];                   // accum
__device__ float g_e[BATCH * PIX];                       // raw scores
__device__ float g_hall[(size_t)MROWS * DECD];
__device__ float g_emball[(size_t)MROWS * EMBD];         // 4 MB
__device__ float g_giemb[(size_t)MROWS * GATE_N];        // 12.2 MB (includes b_ih)
__device__ float g_zbias[GATE_N];
// pre-split tf32 hi/lo for the h-side GEMM: rows [W_hh(1536); W_dec(512)]
__device__ float g_whh_hi[(size_t)2048 * DECD];
__device__ float g_whh_lo[(size_t)2048 * DECD];

// ---------------- utility ----------------
__global__ void zerok(float* p, int n) {
    int i = blockIdx.x * blockDim.x + threadIdx.x;
    if (i < n) p[i] = 0.f;
}

__device__ __forceinline__ unsigned int f2tf32(float f) {
    unsigned int r;
    asm("cvt.rna.tf32.f32 %0, %1;" : "=r"(r) : "f"(f));
    return r;
}

__device__ __forceinline__ float tanh_fast(float x) {
    float y;
    asm("tanh.approx.f32 %0, %1;" : "=f"(y) : "f"(x));
    return y;
}

__device__ __forceinline__ void mma_tf32(float* c,
    unsigned int a0, unsigned int a1, unsigned int a2, unsigned int a3,
    unsigned int b0, unsigned int b1)
{
    asm("mma.sync.aligned.m16n8k8.row.col.f32.tf32.tf32.f32 "
        "{%0,%1,%2,%3}, {%4,%5,%6,%7}, {%8,%9}, {%0,%1,%2,%3};"
        : "+f"(c[0]), "+f"(c[1]), "+f"(c[2]), "+f"(c[3])
        : "r"(a0), "r"(a1), "r"(a2), "r"(a3), "r"(b0), "r"(b1));
}

// ---------------- one-time weight hi/lo split ------------------------------
__global__ void prep_split_hh(const float* __restrict__ W_hh,
                              const float* __restrict__ W_dec) {
    int i = blockIdx.x * 256 + threadIdx.x;
    if (i >= 2048 * DECD) return;
    int n = i / DECD, k = i % DECD;
    float v = (n < GATE_N) ? W_hh[(size_t)n * DECD + k]
                           : W_dec[(size_t)(n - GATE_N) * DECD + k];
    unsigned int hi = f2tf32(v);
    float hif = __uint_as_float(hi);
    g_whh_hi[i] = hif;
    g_whh_lo[i] = __uint_as_float(f2tf32(v - hif));
}

// ---------------- tf32 GEMM: C = A * B^T + bias, tile 128x64, pipelined ----
// (R8-measured: 26.3 GF in 42us -> kept byte-identical)
template <int REMAP>
__global__ __launch_bounds__(256) void gemm_tf32(
    const float* __restrict__ A, int lda,
    const float* __restrict__ Bm, int ldb,
    const float* __restrict__ bias, float* __restrict__ C,
    int M, int N, int K)
{
    __shared__ unsigned int sA[128][36];
    __shared__ unsigned int sB[64][36];
    const int tid = threadIdx.x;
    const int warp = tid >> 5, lane = tid & 31;
    const int m0 = blockIdx.x * 128, n0 = blockIdx.y * 64;
    const int wm = (warp >> 1) * 32;
    const int wn = (warp & 1) * 32;
    const int gid = lane >> 2;
    const int tig = lane & 3;

    float acc[2][4][4];
#pragma unroll
    for (int mt = 0; mt < 2; mt++)
#pragma unroll
        for (int nt = 0; nt < 4; nt++)
#pragma unroll
            for (int r = 0; r < 4; r++) acc[mt][nt][r] = 0.f;

    const float4 z4 = make_float4(0.f, 0.f, 0.f, 0.f);
    float4 fA[4], fB[2];

#pragma unroll
    for (int it = 0; it < 4; it++) {
        int v = tid + it * 256, row = v >> 3, c4 = v & 7, gm = m0 + row;
        fA[it] = (gm < M) ? *(const float4*)&A[(size_t)gm * lda + c4 * 4] : z4;
    }
#pragma unroll
    for (int it = 0; it < 2; it++) {
        int v = tid + it * 256, row = v >> 3, c4 = v & 7, gn = n0 + row;
        fB[it] = (gn < N) ? *(const float4*)&Bm[(size_t)gn * ldb + c4 * 4] : z4;
    }

    for (int kc = 0; kc < K; kc += 32) {
#pragma unroll
        for (int it = 0; it < 4; it++) {
            int v = tid + it * 256, row = v >> 3, c4 = v & 7;
            unsigned int* d = &sA[row][c4 * 4];
            d[0] = f2tf32(fA[it].x); d[1] = f2tf32(fA[it].y);
            d[2] = f2tf32(fA[it].z); d[3] = f2tf32(fA[it].w);
        }
#pragma unroll
        for (int it = 0; it < 2; it++) {
            int v = tid + it * 256, row = v >> 3, c4 = v & 7;
            unsigned int* d = &sB[row][c4 * 4];
            d[0] = f2tf32(fB[it].x); d[1] = f2tf32(fB[it].y);
            d[2] = f2tf32(fB[it].z); d[3] = f2tf32(fB[it].w);
        }
        __syncthreads();

        if (kc + 32 < K) {
            const int kn = kc + 32;
#pragma unroll
            for (int it = 0; it < 4; it++) {
                int v = tid + it * 256, row = v >> 3, c4 = v & 7, gm = m0 + row;
                fA[it] = (gm < M) ? *(const float4*)&A[(size_t)gm * lda + kn + c4 * 4] : z4;
            }
#pragma unroll
            for (int it = 0; it < 2; it++) {
                int v = tid + it * 256, row = v >> 3, c4 = v & 7, gn = n0 + row;
                fB[it] = (gn < N) ? *(const float4*)&Bm[(size_t)gn * ldb + kn + c4 * 4] : z4;
            }
        }

#pragma unroll
        for (int k8 = 0; k8 < 4; k8++) {
            const int kb = k8 * 8;
            unsigned int b0[4], b1[4];
#pragma unroll
            for (int nt = 0; nt < 4; nt++) {
                int rB = wn + nt * 8 + gid;
                b0[nt] = sB[rB][kb + tig];
                b1[nt] = sB[rB][kb + tig + 4];
            }
#pragma unroll
            for (int mt = 0; mt < 2; mt++) {
                int rA = wm + mt * 16 + gid;
                unsigned int a0 = sA[rA][kb + tig];
                unsigned int a1 = sA[rA + 8][kb + tig];
                unsigned int a2 = sA[rA][kb + tig + 4];
                unsigned int a3 = sA[rA + 8][kb + tig + 4];
#pragma unroll
                for (int nt = 0; nt < 4; nt++)
                    mma_tf32(acc[mt][nt], a0, a1, a2, a3, b0[nt], b1[nt]);
            }
        }
        __syncthreads();
    }

#pragma unroll
    for (int mt = 0; mt < 2; mt++) {
#pragma unroll
        for (int half = 0; half < 2; half++) {
            int gm = m0 + wm + mt * 16 + gid + half * 8;
            if (gm >= M) continue;
            size_t base;
            if (REMAP) {
                int t = gm >> 6, bb = gm & 63;
                base = ((size_t)bb * NSTEP + t) * VOC;
            } else {
                base = (size_t)gm * N;
            }
#pragma unroll
            for (int nt = 0; nt < 4; nt++) {
                int gn = n0 + wn + nt * 8 + tig * 2;
                if (gn < N)     C[base + gn]     = acc[mt][nt][half * 2 + 0] + bias[gn];
                if (gn + 1 < N) C[base + gn + 1] = acc[mt][nt][half * 2 + 1] + bias[gn + 1];
            }
        }
    }
}

// ---------------- per-step h-side GEMM: [gh | att2] = h @ [W_hh;W_dec]^T ---
// M=64, N=2048, K=512 (4-way split-K). 3xTF32 w/ pre-split weights.
// atomicAdd into g_gates[gh] / g_att2 (cleared by gru_gates).
__global__ __launch_bounds__(256) void gate_gemm0()
{
    const int n0 = blockIdx.x * 128;
    const int k0 = blockIdx.y * 128;

    __shared__ unsigned int sAhi[64][36], sAlo[64][36];
    __shared__ unsigned int sBhi[128][36], sBlo[128][36];
    const int tid = threadIdx.x;
    const int warp = tid >> 5, lane = tid & 31;
    const int wm = (warp & 1) * 32;
    const int wn = (warp >> 1) * 32;
    const int gid = lane >> 2;
    const int tig = lane & 3;

    float acc[2][4][4];
#pragma unroll
    for (int mt = 0; mt < 2; mt++)
#pragma unroll
        for (int nt = 0; nt < 4; nt++)
#pragma unroll
            for (int r = 0; r < 4; r++) acc[mt][nt][r] = 0.f;

    for (int kc = 0; kc < 128; kc += 32) {
#pragma unroll
        for (int it = 0; it < 2; it++) {
            int v = tid + it * 256, row = v >> 3, c4 = v & 7;
            float4 f = *(const float4*)&g_h[(size_t)row * DECD + k0 + kc + c4 * 4];
            float fv[4] = {f.x, f.y, f.z, f.w};
            unsigned int* dh = &sAhi[row][c4 * 4];
            unsigned int* dl = &sAlo[row][c4 * 4];
#pragma unroll
            for (int j = 0; j < 4; j++) {
                unsigned int hi = f2tf32(fv[j]);
                dh[j] = hi;
                dl[j] = f2tf32(fv[j] - __uint_as_float(hi));
            }
        }
#pragma unroll
        for (int it = 0; it < 4; it++) {
            int v = tid + it * 256, row = v >> 3, c4 = v & 7;
            size_t off = (size_t)(n0 + row) * DECD + k0 + kc + c4 * 4;
            float4 h4 = *(const float4*)&g_whh_hi[off];
            float4 l4 = *(const float4*)&g_whh_lo[off];
            unsigned int* dh = &sBhi[row][c4 * 4];
            unsigned int* dl = &sBlo[row][c4 * 4];
            dh[0] = __float_as_uint(h4.x); dh[1] = __float_as_uint(h4.y);
            dh[2] = __float_as_uint(h4.z); dh[3] = __float_as_uint(h4.w);
            dl[0] = __float_as_uint(l4.x); dl[1] = __float_as_uint(l4.y);
            dl[2] = __float_as_uint(l4.z); dl[3] = __float_as_uint(l4.w);
        }
        __syncthreads();

#pragma unroll
        for (int k8 = 0; k8 < 4; k8++) {
            const int kb = k8 * 8;
            unsigned int bh0[4], bh1[4], bl0[4], bl1[4];
#pragma unroll
            for (int nt = 0; nt < 4; nt++) {
                int rB = wn + nt * 8 + gid;
                bh0[nt] = sBhi[rB][kb + tig];
                bh1[nt] = sBhi[rB][kb + tig + 4];
                bl0[nt] = sBlo[rB][kb + tig];
                bl1[nt] = sBlo[rB][kb + tig + 4];
            }
#pragma unroll
            for (int mt = 0; mt < 2; mt++) {
                int rA = wm + mt * 16 + gid;
                unsigned int ah0 = sAhi[rA][kb + tig];
                unsigned int ah1 = sAhi[rA + 8][kb + tig];
                unsigned int ah2 = sAhi[rA][kb + tig + 4];
                unsigned int ah3 = sAhi[rA + 8][kb + tig + 4];
                unsigned int al0 = sAlo[rA][kb + tig];
                unsigned int al1 = sAlo[rA + 8][kb + tig];
                unsigned int al2 = sAlo[rA][kb + tig + 4];
                unsigned int al3 = sAlo[rA + 8][kb + tig + 4];
#pragma unroll
                for (int nt = 0; nt < 4; nt++) {
                    mma_tf32(acc[mt][nt], ah0, ah1, ah2, ah3, bl0[nt], bl1[nt]);
                    mma_tf32(acc[mt][nt], al0, al1, al2, al3, bh0[nt], bh1[nt]);
                    mma_tf32(acc[mt][nt], ah0, ah1, ah2, ah3, bh0[nt], bh1[nt]);
                }
            }
        }
        __syncthreads();
    }

    float* gh = g_gates + (size_t)BATCH * GATE_N;
#pragma unroll
    for (int mt = 0; mt < 2; mt++)
#pragma unroll
        for (int half = 0; half < 2; half++) {
            int gm = wm + mt * 16 + gid + half * 8;      // 0..63
#pragma unroll
            for (int nt = 0; nt < 4; nt++) {
                int gn = n0 + wn + nt * 8 + tig * 2;
                float v0 = acc[mt][nt][half * 2 + 0];
                float v1 = acc[mt][nt][half * 2 + 1];
                if (gn < GATE_N) {
                    atomicAdd(&gh[(size_t)gm * GATE_N + gn],     v0);
                    atomicAdd(&gh[(size_t)gm * GATE_N + gn + 1], v1);
                } else {
                    atomicAdd(&g_att2[gm * ATTD + gn - GATE_N],     v0);
                    atomicAdd(&g_att2[gm * ATTD + gn - GATE_N + 1], v1);
                }
            }
        }
}

// ---------------- raw attention scores: grid (64, 2) -----------------------
__global__ __launch_bounds__(256) void attn_scores(
    const float* __restrict__ b_dec,
    const float* __restrict__ w_full, const float* __restrict__ b_full)
{
    const int b = blockIdx.x;
    const int y = blockIdx.y;            // pixel half: [y*98, y*98+98)
    const int tid = threadIdx.x;
    const int lane = tid & 31, warp = tid >> 5;
    __shared__ __align__(16) float satt2[ATTD];

    for (int a = tid; a < ATTD; a += 256)
        satt2[a] = g_att2[b * ATTD + a] + b_dec[a];
    __syncthreads();

    const float* att1b = g_att1 + (size_t)b * PIX * ATTD;
    const float4* satt2v = (const float4*)satt2;
    const float4* wfv = (const float4*)w_full;
    const int pbeg = y * 98, pend = pbeg + 98;
    const float bf = b_full[0];
    for (int p = pbeg + warp; p < pend; p += 8) {
        const float4* ar = (const float4*)(att1b + (size_t)p * ATTD);
        float s = 0.f;
#pragma unroll
        for (int a = lane; a < 128; a += 32) {
            float4 x = ar[a]; float4 t2 = satt2v[a]; float4 w = wfv[a];
            s += tanh_fast(x.x + t2.x) * w.x + tanh_fast(x.y + t2.y) * w.y
               + tanh_fast(x.z + t2.z) * w.z + tanh_fast(x.w + t2.w) * w.w;
        }
#pragma unroll
        for (int o = 16; o; o >>= 1) s += __shfl_xor_sync(0xffffffffu, s, o);
        if (lane == 0) g_e[b * PIX + p] = s + bf;
    }
}

// ---------------- softmax + gi = ge + alpha @ encW : grid (64, 3) ----------
// Block = 128 threads, owns 512 gi columns (128 float4). Softmax over 196
// raw scores recomputed in-block (cheap); scale-at-end avoids alpha array.
__global__ __launch_bounds__(128) void ctx_gemm(int t)
{
    const int b = blockIdx.x;
    const int chunk = blockIdx.y;        // 0..2
    const int tid = threadIdx.x;
    const int lane = tid & 31, warp = tid >> 5;
    __shared__ __align__(16) float sa[PIX];   // exp(e - max)
    __shared__ float sred[8];

    for (int i = tid; i < PIX; i += 128) sa[i] = g_e[b * PIX + i];
    __syncthreads();

    float m = -3.4e38f;
    for (int i = tid; i < PIX; i += 128) m = fmaxf(m, sa[i]);
#pragma unroll
    for (int o = 16; o; o >>= 1) m = fmaxf(m, __shfl_xor_sync(0xffffffffu, m, o));
    if (lane == 0) sred[warp] = m;
    __syncthreads();
    if (warp == 0) {
        float v = (lane < 4) ? sred[lane] : -3.4e38f;
#pragma unroll
        for (int o = 16; o; o >>= 1) v = fmaxf(v, __shfl_xor_sync(0xffffffffu, v, o));
        if (lane == 0) sred[4] = v;
    }
    __syncthreads();
    const float M = sred[4];
    float s = 0.f;
    for (int i = tid; i < PIX; i += 128) {
        float ex = expf(sa[i] - M);
        sa[i] = ex;
        s += ex;
    }
#pragma unroll
    for (int o = 16; o; o >>= 1) s += __shfl_xor_sync(0xffffffffu, s, o);
    if (lane == 0) sred[warp] = s;
    __syncthreads();
    if (warp == 0) {
        float v = (lane < 4) ? sred[lane] : 0.f;
#pragma unroll
        for (int o = 16; o; o >>= 1) v += __shfl_xor_sync(0xffffffffu, v, o);
        if (lane == 0) sred[5] = v;
    }
    __syncthreads();
    const float inv = 1.f / sred[5];

    // acc = sum_p exp_p * encW[b,p, chunk*512 + tid*4 ...]; PIX = 49*4
    const float4* ew = (const float4*)g_encw + ((size_t)b * PIX) * 384
                       + chunk * 128 + tid;
    float4 acc = make_float4(0.f, 0.f, 0.f, 0.f);
#pragma unroll 1
    for (int p = 0; p < PIX; p += 4) {
        float a0 = sa[p], a1 = sa[p + 1], a2 = sa[p + 2], a3 = sa[p + 3];
        float4 v0 = ew[(size_t)p * 384];
        float4 v1 = ew[(size_t)(p + 1) * 384];
        float4 v2 = ew[(size_t)(p + 2) * 384];
        float4 v3 = ew[(size_t)(p + 3) * 384];
        acc.x += a0 * v0.x + a1 * v1.x + a2 * v2.x + a3 * v3.x;
        acc.y += a0 * v0.y + a1 * v1.y + a2 * v2.y + a3 * v3.y;
        acc.z += a0 * v0.z + a1 * v1.z + a2 * v2.z + a3 * v3.z;
        acc.w += a0 * v0.w + a1 * v1.w + a2 * v2.w + a3 * v3.w;
    }
    float4 ge4 = ((const float4*)(g_giemb + ((size_t)t * BATCH + b) * GATE_N))[chunk * 128 + tid];
    float4 outv = make_float4(acc.x * inv + ge4.x, acc.y * inv + ge4.y,
                              acc.z * inv + ge4.z, acc.w * inv + ge4.w);
    ((float4*)(g_gates + (size_t)b * GATE_N))[chunk * 128 + tid] = outv;
}

// ---------------- GRU gates + h update + clear accumulators ----------------
__global__ __launch_bounds__(256) void gru_gates(
    int t, const float* __restrict__ b_hh)
{
    int idx = blockIdx.x * 256 + threadIdx.x;
    if (idx >= BATCH * DECD) return;
    int b = idx >> 9, d = idx & 511;
    const float* gi = g_gates + (size_t)b * GATE_N;
    float* gh = g_gates + (size_t)BATCH * GATE_N + (size_t)b * GATE_N;
    float rr = gi[d] + (gh[d] + b_hh[d]);
    float zz = gi[512 + d] + (gh[512 + d] + b_hh[512 + d]);
    float inp = gi[1024 + d];
    float hnp = gh[1024 + d] + b_hh[1024 + d];
    // clear accumulators for next step's atomic GEMM
    gh[d] = 0.f; gh[512 + d] = 0.f; gh[1024 + d] = 0.f;
    g_att2[b * ATTD + d] = 0.f;
    float r = 1.f / (1.f + expf(-rr));
    float z = 1.f / (1.f + expf(-zz));
    float n = tanhf(inp + r * hnp);
    float hold = g_h[b * DECD + d];
    float hnew = (1.f - z) * n + z * hold;
    g_h[b * DECD + d] = hnew;
    g_hall[((size_t)t * BATCH + b) * DECD + d] = hnew;
}

// ---------------- embedding gather for all steps ---------------------------
__global__ __launch_bounds__(128) void gather_embs(
    const int* __restrict__ captions, const float* __restrict__ emb_table)
{
    int r = blockIdx.x;          // t*64+b
    int t = r >> 6, b = r & 63;
    int tok = captions[b * TT + t];
    const float4* src = (const float4*)(emb_table + (size_t)tok * EMBD);
    ((float4*)(g_emball + (size_t)r * EMBD))[threadIdx.x] = src[threadIdx.x];
}

__global__ void write_caplens(const int* __restrict__ caplens, float* __restrict__ out, int n)
{
    int i = threadIdx.x;
    if (i < n && i < BATCH) out[i] = (float)(caplens[i] - 1);
}

// ---------------- host ----------------
extern "C" void kernel_launch(void* const* d_in, const int* in_sizes, int n_in,
                              void* d_out, int out_size)
{
    const float* enc       = (const float*)d_in[0];
    const int*   captions  = (const int*)  d_in[1];
    const int*   caplens   = (const int*)  d_in[2];
    const float* emb_table = (const float*)d_in[3];
    const float* W_enc     = (const float*)d_in[4];
    const float* b_enc     = (const float*)d_in[5];
    const float* W_dec     = (const float*)d_in[6];
    const float* b_dec     = (const float*)d_in[7];
    const float* w_full    = (const float*)d_in[8];
    const float* b_full    = (const float*)d_in[9];
    const float* W_ih      = (const float*)d_in[10];
    const float* b_ih      = (const float*)d_in[11];
    const float* W_hh      = (const float*)d_in[12];
    const float* b_hh      = (const float*)d_in[13];
    const float* W_fc      = (const float*)d_in[14];
    const float* b_fc      = (const float*)d_in[15];
    float* out = (float*)d_out;

    float *att1p, *encwp, *hp, *hallp, *emballp, *giembp, *gatesp, *att2p, *zbp;
    cudaGetSymbolAddress((void**)&att1p, g_att1);
    cudaGetSymbolAddress((void**)&encwp, g_encw);
    cudaGetSymbolAddress((void**)&hp, g_h);
    cudaGetSymbolAddress((void**)&hallp, g_hall);
    cudaGetSymbolAddress((void**)&emballp, g_emball);
    cudaGetSymbolAddress((void**)&giembp, g_giemb);
    cudaGetSymbolAddress((void**)&gatesp, g_gates);
    cudaGetSymbolAddress((void**)&att2p, g_att2);
    cudaGetSymbolAddress((void**)&zbp, g_zbias);

    // initial zeros: h0, gh accumulator, att2 accumulator, zero-bias
    zerok<<<(BATCH * DECD + 255) / 256, 256>>>(hp, BATCH * DECD);
    zerok<<<(BATCH * GATE_N + 255) / 256, 256>>>(gatesp + BATCH * GATE_N, BATCH * GATE_N);
    zerok<<<(BATCH * ATTD + 255) / 256, 256>>>(att2p, BATCH * ATTD);
    zerok<<<(GATE_N + 255) / 256, 256>>>(zbp, GATE_N);

    // one-time prep
    gather_embs<<<MROWS, 128>>>(captions, emb_table);
    prep_split_hh<<<(2048 * DECD + 255) / 256, 256>>>(W_hh, W_dec);

    // att1 = enc @ W_enc^T + b_enc : [12544,2048]x[2048,512]
    gemm_tf32<0><<<dim3(98, 8), 256>>>(enc, ENCD, W_enc, ENCD, b_enc, att1p,
                                       BATCH * PIX, ATTD, ENCD);

    // encW = enc @ W_ih[:,512:2560]^T : [12544,2048]x[2048,1536]
    gemm_tf32<0><<<dim3(98, 24), 256>>>(enc, ENCD, W_ih + 512, 2560, zbp, encwp,
                                        BATCH * PIX, GATE_N, ENCD);

    // gi_emb = embs @ W_ih[:, :512]^T + b_ih : [1984,512]x[512,1536]
    gemm_tf32<0><<<dim3(16, 24), 256>>>(emballp, EMBD, W_ih, 2560,
                                        b_ih, giembp, MROWS, GATE_N, EMBD);

    for (int t = 0; t < NSTEP; t++) {
        gate_gemm0<<<dim3(16, 4), 256>>>();                 // gh + att2 from h_{t-1}
        attn_scores<<<dim3(BATCH, 2), 256>>>(b_dec, w_full, b_full);
        ctx_gemm<<<dim3(BATCH, 3), 128>>>(t);               // softmax + gi
        gru_gates<<<(BATCH * DECD + 255) / 256, 256>>>(t, b_hh);
    }

    // logits = h_all @ W_fc^T + b_fc, stored as [b, t, v]
    gemm_tf32<1><<<dim3(16, 469), 256>>>(hallp, DECD, W_fc, DECD, b_fc, out,
                                         MROWS, VOC, DECD);

    long long NLOG = (long long)BATCH * NSTEP * VOC;
    if ((long long)out_size > NLOG) {
        int rem = (int)((long long)out_size - NLOG);
        write_caplens<<<1, 64>>>(caplens, out + NLOG, rem);
    }
}

// round 16
// speedup vs baseline: 1.2890x; 1.2890x over previous
#include <cuda_runtime.h>
#include <cuda_fp16.h>

#define BATCH 64
#define PIX   196
#define ENCD  2048
#define ATTD  512
#define DECD  512
#define EMBD  512
#define TT    32
#define NSTEP 31
#define VOC   30000
#define GATE_N 1536
#define CATN  2048              // [W_hh(1536); W_dec(512)]
#define MROWS (NSTEP * BATCH)   // 1984

// ---------------- device scratch ----------------
__device__ __half g_att1h[(size_t)BATCH * PIX * ATTD];   // 12.8 MB fp16
__device__ __half g_encwh[(size_t)BATCH * PIX * GATE_N]; // 25.7 MB fp16
__device__ float g_h[BATCH * DECD];
__device__ float g_gi[BATCH * GATE_N];
__device__ float g_ghatt2[BATCH * CATN];       // per-b: gh[1536] | att2[512]
__device__ float g_e[BATCH * PIX];
__device__ float g_hall[(size_t)MROWS * DECD];
__device__ float g_emball[(size_t)MROWS * EMBD];
__device__ float g_giemb[(size_t)MROWS * GATE_N];   // includes b_ih
__device__ float g_whhcat[(size_t)CATN * DECD];     // [W_hh; W_dec]
__device__ float g_biascat[CATN];                   // [0...0, b_dec]
__device__ float g_zbias[GATE_N];

// ---------------- utility ----------------
__global__ void zerok(float* p, int n) {
    int i = blockIdx.x * blockDim.x + threadIdx.x;
    if (i < n) p[i] = 0.f;
}

__device__ __forceinline__ unsigned int f2tf32(float f) {
    unsigned int r;
    asm("cvt.rna.tf32.f32 %0, %1;" : "=r"(r) : "f"(f));
    return r;
}

__device__ __forceinline__ float tanh_fast(float x) {
    float y;
    asm("tanh.approx.f32 %0, %1;" : "=f"(y) : "f"(x));
    return y;
}

__device__ __forceinline__ void mma_tf32(float* c,
    unsigned int a0, unsigned int a1, unsigned int a2, unsigned int a3,
    unsigned int b0, unsigned int b1)
{
    asm("mma.sync.aligned.m16n8k8.row.col.f32.tf32.tf32.f32 "
        "{%0,%1,%2,%3}, {%4,%5,%6,%7}, {%8,%9}, {%0,%1,%2,%3};"
        : "+f"(c[0]), "+f"(c[1]), "+f"(c[2]), "+f"(c[3])
        : "r"(a0), "r"(a1), "r"(a2), "r"(a3), "r"(b0), "r"(b1));
}

// ---------------- one-time: build [W_hh;W_dec] + bias ----------------------
__global__ void prep_cat(const float* __restrict__ W_hh,
                         const float* __restrict__ W_dec,
                         const float* __restrict__ b_dec) {
    int i = blockIdx.x * 256 + threadIdx.x;
    if (i < CATN * DECD) {
        int n = i / DECD, k = i % DECD;
        g_whhcat[i] = (n < GATE_N) ? W_hh[(size_t)n * DECD + k]
                                   : W_dec[(size_t)(n - GATE_N) * DECD + k];
    }
    if (i < CATN) g_biascat[i] = (i < GATE_N) ? 0.f : b_dec[i - GATE_N];
}

// ---------------- tf32 GEMM: C = A * B^T + bias, tile 128x64, pipelined ----
// OUTMODE: 0 = f32, 1 = f32 with [t*64+b -> (b*31+t)*VOC] remap, 2 = fp16.
template <int OUTMODE>
__global__ __launch_bounds__(256) void gemm_tf32(
    const float* __restrict__ A, int lda,
    const float* __restrict__ Bm, int ldb,
    const float* __restrict__ bias, void* __restrict__ Cv,
    int M, int N, int K)
{
    __shared__ unsigned int sA[128][36];
    __shared__ unsigned int sB[64][36];
    const int tid = threadIdx.x;
    const int warp = tid >> 5, lane = tid & 31;
    const int m0 = blockIdx.x * 128, n0 = blockIdx.y * 64;
    const int wm = (warp >> 1) * 32;
    const int wn = (warp & 1) * 32;
    const int gid = lane >> 2;
    const int tig = lane & 3;

    float acc[2][4][4];
#pragma unroll
    for (int mt = 0; mt < 2; mt++)
#pragma unroll
        for (int nt = 0; nt < 4; nt++)
#pragma unroll
            for (int r = 0; r < 4; r++) acc[mt][nt][r] = 0.f;

    const float4 z4 = make_float4(0.f, 0.f, 0.f, 0.f);
    float4 fA[4], fB[2];

#pragma unroll
    for (int it = 0; it < 4; it++) {
        int v = tid + it * 256, row = v >> 3, c4 = v & 7, gm = m0 + row;
        fA[it] = (gm < M) ? *(const float4*)&A[(size_t)gm * lda + c4 * 4] : z4;
    }
#pragma unroll
    for (int it = 0; it < 2; it++) {
        int v = tid + it * 256, row = v >> 3, c4 = v & 7, gn = n0 + row;
        fB[it] = (gn < N) ? *(const float4*)&Bm[(size_t)gn * ldb + c4 * 4] : z4;
    }

    for (int kc = 0; kc < K; kc += 32) {
#pragma unroll
        for (int it = 0; it < 4; it++) {
            int v = tid + it * 256, row = v >> 3, c4 = v & 7;
            unsigned int* d = &sA[row][c4 * 4];
            d[0] = f2tf32(fA[it].x); d[1] = f2tf32(fA[it].y);
            d[2] = f2tf32(fA[it].z); d[3] = f2tf32(fA[it].w);
        }
#pragma unroll
        for (int it = 0; it < 2; it++) {
            int v = tid + it * 256, row = v >> 3, c4 = v & 7;
            unsigned int* d = &sB[row][c4 * 4];
            d[0] = f2tf32(fB[it].x); d[1] = f2tf32(fB[it].y);
            d[2] = f2tf32(fB[it].z); d[3] = f2tf32(fB[it].w);
        }
        __syncthreads();

        if (kc + 32 < K) {
            const int kn = kc + 32;
#pragma unroll
            for (int it = 0; it < 4; it++) {
                int v = tid + it * 256, row = v >> 3, c4 = v & 7, gm = m0 + row;
                fA[it] = (gm < M) ? *(const float4*)&A[(size_t)gm * lda + kn + c4 * 4] : z4;
            }
#pragma unroll
            for (int it = 0; it < 2; it++) {
                int v = tid + it * 256, row = v >> 3, c4 = v & 7, gn = n0 + row;
                fB[it] = (gn < N) ? *(const float4*)&Bm[(size_t)gn * ldb + kn + c4 * 4] : z4;
            }
        }

#pragma unroll
        for (int k8 = 0; k8 < 4; k8++) {
            const int kb = k8 * 8;
            unsigned int b0[4], b1[4];
#pragma unroll
            for (int nt = 0; nt < 4; nt++) {
                int rB = wn + nt * 8 + gid;
                b0[nt] = sB[rB][kb + tig];
                b1[nt] = sB[rB][kb + tig + 4];
            }
#pragma unroll
            for (int mt = 0; mt < 2; mt++) {
                int rA = wm + mt * 16 + gid;
                unsigned int a0 = sA[rA][kb + tig];
                unsigned int a1 = sA[rA + 8][kb + tig];
                unsigned int a2 = sA[rA][kb + tig + 4];
                unsigned int a3 = sA[rA + 8][kb + tig + 4];
#pragma unroll
                for (int nt = 0; nt < 4; nt++)
                    mma_tf32(acc[mt][nt], a0, a1, a2, a3, b0[nt], b1[nt]);
            }
        }
        __syncthreads();
    }

#pragma unroll
    for (int mt = 0; mt < 2; mt++) {
#pragma unroll
        for (int half = 0; half < 2; half++) {
            int gm = m0 + wm + mt * 16 + gid + half * 8;
            if (gm >= M) continue;
#pragma unroll
            for (int nt = 0; nt < 4; nt++) {
                int gn = n0 + wn + nt * 8 + tig * 2;
                if (gn >= N) continue;
                float v0 = acc[mt][nt][half * 2 + 0] + bias[gn];
                float v1 = acc[mt][nt][half * 2 + 1] + bias[gn + 1];
                if (OUTMODE == 1) {
                    int t = gm >> 6, bb = gm & 63;
                    size_t base = ((size_t)bb * NSTEP + t) * VOC;
                    float* C = (float*)Cv;
                    C[base + gn] = v0; C[base + gn + 1] = v1;
                } else if (OUTMODE == 0) {
                    float* C = (float*)Cv;
                    size_t base = (size_t)gm * N;
                    C[base + gn] = v0; C[base + gn + 1] = v1;
                } else {
                    __half2* C = (__half2*)Cv;
                    C[((size_t)gm * N + gn) >> 1] = __floats2half2_rn(v0, v1);
                }
            }
        }
    }
}

// ---------------- attention scores: grid (64, 2), 256 thr ------------------
// e[b,p] = w_full . tanh(att1h[b,p,:] + att2[b,:]) + b_full
// att2 (incl b_dec) lives at g_ghatt2[b*2048 + 1536 ...].
__global__ __launch_bounds__(256) void attn_scores(
    const float* __restrict__ w_full, const float* __restrict__ b_full)
{
    const int b = blockIdx.x;
    const int y = blockIdx.y;
    const int tid = threadIdx.x;
    const int lane = tid & 31, warp = tid >> 5;
    __shared__ __align__(16) float satt2[ATTD];

    for (int a = tid; a < ATTD; a += 256)
        satt2[a] = g_ghatt2[b * CATN + GATE_N + a];
    __syncthreads();

    const float2* satt2v = (const float2*)satt2;
    const float2* wfv = (const float2*)w_full;
    const int pbeg = y * 98, pend = pbeg + 98;
    const float bf = b_full[0];
    for (int p = pbeg + warp; p < pend; p += 8) {
        const __half2* ar = (const __half2*)(g_att1h + ((size_t)b * PIX + p) * ATTD);
        float s = 0.f;
#pragma unroll
        for (int a = lane; a < 256; a += 32) {
            float2 x = __half22float2(ar[a]);
            float2 t2 = satt2v[a];
            float2 w = wfv[a];
            s += tanh_fast(x.x + t2.x) * w.x + tanh_fast(x.y + t2.y) * w.y;
        }
#pragma unroll
        for (int o = 16; o; o >>= 1) s += __shfl_xor_sync(0xffffffffu, s, o);
        if (lane == 0) g_e[b * PIX + p] = s + bf;
    }
}

// ---------------- softmax + gi = giemb + alpha @ encW(fp16): grid (64,3) ---
__global__ __launch_bounds__(256) void ctx_gi(int t)
{
    const int b = blockIdx.x;
    const int chunk = blockIdx.y;        // 0..2, 512 cols each
    const int tid = threadIdx.x;
    const int lane = tid & 31, warp = tid >> 5;
    __shared__ __align__(16) float sa[PIX];
    __shared__ float sred[12];

    for (int i = tid; i < PIX; i += 256) sa[i] = g_e[b * PIX + i];
    __syncthreads();

    float m = -3.4e38f;
    for (int i = tid; i < PIX; i += 256) m = fmaxf(m, sa[i]);
#pragma unroll
    for (int o = 16; o; o >>= 1) m = fmaxf(m, __shfl_xor_sync(0xffffffffu, m, o));
    if (lane == 0) sred[warp] = m;
    __syncthreads();
    if (warp == 0) {
        float v = (lane < 8) ? sred[lane] : -3.4e38f;
#pragma unroll
        for (int o = 16; o; o >>= 1) v = fmaxf(v, __shfl_xor_sync(0xffffffffu, v, o));
        if (lane == 0) sred[8] = v;
    }
    __syncthreads();
    const float M = sred[8];
    float s = 0.f;
    for (int i = tid; i < PIX; i += 256) {
        float ex = expf(sa[i] - M);
        sa[i] = ex;
        s += ex;
    }
#pragma unroll
    for (int o = 16; o; o >>= 1) s += __shfl_xor_sync(0xffffffffu, s, o);
    if (lane == 0) sred[warp] = s;
    __syncthreads();
    if (warp == 0) {
        float v = (lane < 8) ? sred[lane] : 0.f;
#pragma unroll
        for (int o = 16; o; o >>= 1) v += __shfl_xor_sync(0xffffffffu, v, o);
        if (lane == 0) sred[9] = v;
    }
    __syncthreads();
    const float inv = 1.f / sred[9];

    // per thread: one half2 column-pair, 196 rows, stride 768 half2
    const __half2* ew = (const __half2*)g_encwh
                        + (size_t)b * PIX * 768 + chunk * 256 + tid;
    float2 acc = make_float2(0.f, 0.f);
#pragma unroll 1
    for (int p = 0; p < PIX; p += 4) {
        float a0 = sa[p], a1 = sa[p + 1], a2 = sa[p + 2], a3 = sa[p + 3];
        float2 v0 = __half22float2(ew[(size_t)p * 768]);
        float2 v1 = __half22float2(ew[(size_t)(p + 1) * 768]);
        float2 v2 = __half22float2(ew[(size_t)(p + 2) * 768]);
        float2 v3 = __half22float2(ew[(size_t)(p + 3) * 768]);
        acc.x += a0 * v0.x + a1 * v1.x + a2 * v2.x + a3 * v3.x;
        acc.y += a0 * v0.y + a1 * v1.y + a2 * v2.y + a3 * v3.y;
    }
    const int col = chunk * 512 + tid * 2;
    float2 ge = *(const float2*)&g_giemb[((size_t)t * BATCH + b) * GATE_N + col];
    float2 outv = make_float2(acc.x * inv + ge.x, acc.y * inv + ge.y);
    *(float2*)&g_gi[(size_t)b * GATE_N + col] = outv;
}

// ---------------- GRU gates + h update -------------------------------------
__global__ __launch_bounds__(256) void gru_gates(
    int t, const float* __restrict__ b_hh)
{
    int idx = blockIdx.x * 256 + threadIdx.x;
    if (idx >= BATCH * DECD) return;
    int b = idx >> 9, d = idx & 511;
    const float* gi = g_gi + (size_t)b * GATE_N;
    const float* gh = g_ghatt2 + (size_t)b * CATN;
    float rr = gi[d] + gh[d] + b_hh[d];
    float zz = gi[512 + d] + gh[512 + d] + b_hh[512 + d];
    float inp = gi[1024 + d];
    float hnp = gh[1024 + d] + b_hh[1024 + d];
    float r = 1.f / (1.f + expf(-rr));
    float z = 1.f / (1.f + expf(-zz));
    float n = tanhf(inp + r * hnp);
    float hold = g_h[b * DECD + d];
    float hnew = (1.f - z) * n + z * hold;
    g_h[b * DECD + d] = hnew;
    g_hall[((size_t)t * BATCH + b) * DECD + d] = hnew;
}

// ---------------- embedding gather -----------------------------------------
__global__ __launch_bounds__(128) void gather_embs(
    const int* __restrict__ captions, const float* __restrict__ emb_table)
{
    int r = blockIdx.x;          // t*64+b
    int t = r >> 6, b = r & 63;
    int tok = captions[b * TT + t];
    const float4* src = (const float4*)(emb_table + (size_t)tok * EMBD);
    ((float4*)(g_emball + (size_t)r * EMBD))[threadIdx.x] = src[threadIdx.x];
}

__global__ void write_caplens(const int* __restrict__ caplens, float* __restrict__ out, int n)
{
    int i = threadIdx.x;
    if (i < n && i < BATCH) out[i] = (float)(caplens[i] - 1);
}

// ---------------- host ----------------
extern "C" void kernel_launch(void* const* d_in, const int* in_sizes, int n_in,
                              void* d_out, int out_size)
{
    const float* enc       = (const float*)d_in[0];
    const int*   captions  = (const int*)  d_in[1];
    const int*   caplens   = (const int*)  d_in[2];
    const float* emb_table = (const float*)d_in[3];
    const float* W_enc     = (const float*)d_in[4];
    const float* b_enc     = (const float*)d_in[5];
    const float* W_dec     = (const float*)d_in[6];
    const float* b_dec     = (const float*)d_in[7];
    const float* w_full    = (const float*)d_in[8];
    const float* b_full    = (const float*)d_in[9];
    const float* W_ih      = (const float*)d_in[10];
    const float* b_ih      = (const float*)d_in[11];
    const float* W_hh      = (const float*)d_in[12];
    const float* b_hh      = (const float*)d_in[13];
    const float* W_fc      = (const float*)d_in[14];
    const float* b_fc      = (const float*)d_in[15];
    float* out = (float*)d_out;

    void *att1hp, *encwhp;
    float *hp, *hallp, *emballp, *giembp, *whhcatp, *biascatp, *zbp, *ghatt2p;
    cudaGetSymbolAddress(&att1hp, g_att1h);
    cudaGetSymbolAddress(&encwhp, g_encwh);
    cudaGetSymbolAddress((void**)&hp, g_h);
    cudaGetSymbolAddress((void**)&hallp, g_hall);
    cudaGetSymbolAddress((void**)&emballp, g_emball);
    cudaGetSymbolAddress((void**)&giembp, g_giemb);
    cudaGetSymbolAddress((void**)&whhcatp, g_whhcat);
    cudaGetSymbolAddress((void**)&biascatp, g_biascat);
    cudaGetSymbolAddress((void**)&zbp, g_zbias);
    cudaGetSymbolAddress((void**)&ghatt2p, g_ghatt2);

    // h0 = 0; zero bias for encW
    zerok<<<(BATCH * DECD + 255) / 256, 256>>>(hp, BATCH * DECD);
    zerok<<<(GATE_N + 255) / 256, 256>>>(zbp, GATE_N);

    // one-time prep
    gather_embs<<<MROWS, 128>>>(captions, emb_table);
    prep_cat<<<(CATN * DECD + 255) / 256, 256>>>(W_hh, W_dec, b_dec);

    // att1 (fp16) = enc @ W_enc^T + b_enc
    gemm_tf32<2><<<dim3(98, 8), 256>>>(enc, ENCD, W_enc, ENCD, b_enc, att1hp,
                                       BATCH * PIX, ATTD, ENCD);

    // encW (fp16) = enc @ W_ih[:,512:2560]^T
    gemm_tf32<2><<<dim3(98, 24), 256>>>(enc, ENCD, W_ih + 512, 2560, zbp, encwhp,
                                        BATCH * PIX, GATE_N, ENCD);

    // gi_emb = embs @ W_ih[:, :512]^T + b_ih
    gemm_tf32<0><<<dim3(16, 24), 256>>>(emballp, EMBD, W_ih, 2560,
                                        b_ih, giembp, MROWS, GATE_N, EMBD);

    for (int t = 0; t < NSTEP; t++) {
        // [gh | att2] = h @ [W_hh; W_dec]^T + [0; b_dec]   (direct store)
        gemm_tf32<0><<<dim3(1, 32), 256>>>(hp, DECD, whhcatp, DECD,
                                           biascatp, ghatt2p, BATCH, CATN, DECD);
        attn_scores<<<dim3(BATCH, 2), 256>>>(w_full, b_full);
        ctx_gi<<<dim3(BATCH, 3), 256>>>(t);
        gru_gates<<<(BATCH * DECD + 255) / 256, 256>>>(t, b_hh);
    }

    // logits = h_all @ W_fc^T + b_fc, stored as [b, t, v]
    gemm_tf32<1><<<dim3(16, 469), 256>>>(hallp, DECD, W_fc, DECD, b_fc, out,
                                         MROWS, VOC, DECD);

    long long NLOG = (long long)BATCH * NSTEP * VOC;
    if ((long long)out_size > NLOG) {
        int rem = (int)((long long)out_size - NLOG);
        write_caplens<<<1, 64>>>(caplens, out + NLOG, rem);
    }
}

// round 17
// speedup vs baseline: 1.3242x; 1.0273x over previous
#include <cuda_runtime.h>
#include <cuda_fp16.h>

#define BATCH 64
#define PIX   196
#define ENCD  2048
#define ATTD  512
#define DECD  512
#define EMBD  512
#define TT    32
#define NSTEP 31
#define VOC   30000
#define GATE_N 1536
#define CATN  2048              // [W_hh(1536); W_dec(512)]
#define MROWS (NSTEP * BATCH)   // 1984

// ---------------- device scratch ----------------
__device__ __half g_att1h[(size_t)BATCH * PIX * ATTD];   // 12.8 MB fp16
__device__ __half g_encwh[(size_t)BATCH * PIX * GATE_N]; // 25.7 MB fp16
__device__ float g_h[BATCH * DECD];
__device__ float g_ghatt2[BATCH * CATN];       // per-b: gh[1536] | att2[512]
__device__ float g_hall[(size_t)MROWS * DECD];
__device__ float g_emball[(size_t)MROWS * EMBD];
__device__ float g_giemb[(size_t)MROWS * GATE_N];   // includes b_ih
__device__ float g_whhcat[(size_t)CATN * DECD];     // [W_hh; W_dec]
__device__ float g_biascat[CATN];                   // [0...0, b_dec]
__device__ float g_zbias[GATE_N];

// ---------------- utility ----------------
__global__ void zerok(float* p, int n) {
    int i = blockIdx.x * blockDim.x + threadIdx.x;
    if (i < n) p[i] = 0.f;
}

__device__ __forceinline__ unsigned int f2tf32(float f) {
    unsigned int r;
    asm("cvt.rna.tf32.f32 %0, %1;" : "=r"(r) : "f"(f));
    return r;
}

__device__ __forceinline__ float tanh_fast(float x) {
    float y;
    asm("tanh.approx.f32 %0, %1;" : "=f"(y) : "f"(x));
    return y;
}

__device__ __forceinline__ void mma_tf32(float* c,
    unsigned int a0, unsigned int a1, unsigned int a2, unsigned int a3,
    unsigned int b0, unsigned int b1)
{
    asm("mma.sync.aligned.m16n8k8.row.col.f32.tf32.tf32.f32 "
        "{%0,%1,%2,%3}, {%4,%5,%6,%7}, {%8,%9}, {%0,%1,%2,%3};"
        : "+f"(c[0]), "+f"(c[1]), "+f"(c[2]), "+f"(c[3])
        : "r"(a0), "r"(a1), "r"(a2), "r"(a3), "r"(b0), "r"(b1));
}

// ---------------- one-time: build [W_hh;W_dec] + bias ----------------------
__global__ void prep_cat(const float* __restrict__ W_hh,
                         const float* __restrict__ W_dec,
                         const float* __restrict__ b_dec) {
    int i = blockIdx.x * 256 + threadIdx.x;
    if (i < CATN * DECD) {
        int n = i / DECD, k = i % DECD;
        g_whhcat[i] = (n < GATE_N) ? W_hh[(size_t)n * DECD + k]
                                   : W_dec[(size_t)(n - GATE_N) * DECD + k];
    }
    if (i < CATN) g_biascat[i] = (i < GATE_N) ? 0.f : b_dec[i - GATE_N];
}

// ---------------- tf32 GEMM: C = A * B^T + bias, tile 128x64, pipelined ----
// OUTMODE: 0 = f32, 1 = f32 with [t*64+b -> (b*31+t)*VOC] remap, 2 = fp16.
template <int OUTMODE>
__global__ __launch_bounds__(256) void gemm_tf32(
    const float* __restrict__ A, int lda,
    const float* __restrict__ Bm, int ldb,
    const float* __restrict__ bias, void* __restrict__ Cv,
    int M, int N, int K)
{
    __shared__ unsigned int sA[128][36];
    __shared__ unsigned int sB[64][36];
    const int tid = threadIdx.x;
    const int warp = tid >> 5, lane = tid & 31;
    const int m0 = blockIdx.x * 128, n0 = blockIdx.y * 64;
    const int wm = (warp >> 1) * 32;
    const int wn = (warp & 1) * 32;
    const int gid = lane >> 2;
    const int tig = lane & 3;

    float acc[2][4][4];
#pragma unroll
    for (int mt = 0; mt < 2; mt++)
#pragma unroll
        for (int nt = 0; nt < 4; nt++)
#pragma unroll
            for (int r = 0; r < 4; r++) acc[mt][nt][r] = 0.f;

    const float4 z4 = make_float4(0.f, 0.f, 0.f, 0.f);
    float4 fA[4], fB[2];

#pragma unroll
    for (int it = 0; it < 4; it++) {
        int v = tid + it * 256, row = v >> 3, c4 = v & 7, gm = m0 + row;
        fA[it] = (gm < M) ? *(const float4*)&A[(size_t)gm * lda + c4 * 4] : z4;
    }
#pragma unroll
    for (int it = 0; it < 2; it++) {
        int v = tid + it * 256, row = v >> 3, c4 = v & 7, gn = n0 + row;
        fB[it] = (gn < N) ? *(const float4*)&Bm[(size_t)gn * ldb + c4 * 4] : z4;
    }

    for (int kc = 0; kc < K; kc += 32) {
#pragma unroll
        for (int it = 0; it < 4; it++) {
            int v = tid + it * 256, row = v >> 3, c4 = v & 7;
            unsigned int* d = &sA[row][c4 * 4];
            d[0] = f2tf32(fA[it].x); d[1] = f2tf32(fA[it].y);
            d[2] = f2tf32(fA[it].z); d[3] = f2tf32(fA[it].w);
        }
#pragma unroll
        for (int it = 0; it < 2; it++) {
            int v = tid + it * 256, row = v >> 3, c4 = v & 7;
            unsigned int* d = &sB[row][c4 * 4];
            d[0] = f2tf32(fB[it].x); d[1] = f2tf32(fB[it].y);
            d[2] = f2tf32(fB[it].z); d[3] = f2tf32(fB[it].w);
        }
        __syncthreads();

        if (kc + 32 < K) {
            const int kn = kc + 32;
#pragma unroll
            for (int it = 0; it < 4; it++) {
                int v = tid + it * 256, row = v >> 3, c4 = v & 7, gm = m0 + row;
                fA[it] = (gm < M) ? *(const float4*)&A[(size_t)gm * lda + kn + c4 * 4] : z4;
            }
#pragma unroll
            for (int it = 0; it < 2; it++) {
                int v = tid + it * 256, row = v >> 3, c4 = v & 7, gn = n0 + row;
                fB[it] = (gn < N) ? *(const float4*)&Bm[(size_t)gn * ldb + kn + c4 * 4] : z4;
            }
        }

#pragma unroll
        for (int k8 = 0; k8 < 4; k8++) {
            const int kb = k8 * 8;
            unsigned int b0[4], b1[4];
#pragma unroll
            for (int nt = 0; nt < 4; nt++) {
                int rB = wn + nt * 8 + gid;
                b0[nt] = sB[rB][kb + tig];
                b1[nt] = sB[rB][kb + tig + 4];
            }
#pragma unroll
            for (int mt = 0; mt < 2; mt++) {
                int rA = wm + mt * 16 + gid;
                unsigned int a0 = sA[rA][kb + tig];
                unsigned int a1 = sA[rA + 8][kb + tig];
                unsigned int a2 = sA[rA][kb + tig + 4];
                unsigned int a3 = sA[rA + 8][kb + tig + 4];
#pragma unroll
                for (int nt = 0; nt < 4; nt++)
                    mma_tf32(acc[mt][nt], a0, a1, a2, a3, b0[nt], b1[nt]);
            }
        }
        __syncthreads();
    }

#pragma unroll
    for (int mt = 0; mt < 2; mt++) {
#pragma unroll
        for (int half = 0; half < 2; half++) {
            int gm = m0 + wm + mt * 16 + gid + half * 8;
            if (gm >= M) continue;
#pragma unroll
            for (int nt = 0; nt < 4; nt++) {
                int gn = n0 + wn + nt * 8 + tig * 2;
                if (gn >= N) continue;
                float v0 = acc[mt][nt][half * 2 + 0] + bias[gn];
                float v1 = acc[mt][nt][half * 2 + 1] + bias[gn + 1];
                if (OUTMODE == 1) {
                    int t = gm >> 6, bb = gm & 63;
                    size_t base = ((size_t)bb * NSTEP + t) * VOC;
                    float* C = (float*)Cv;
                    C[base + gn] = v0; C[base + gn + 1] = v1;
                } else if (OUTMODE == 0) {
                    float* C = (float*)Cv;
                    size_t base = (size_t)gm * N;
                    C[base + gn] = v0; C[base + gn + 1] = v1;
                } else {
                    __half2* C = (__half2*)Cv;
                    C[((size_t)gm * N + gn) >> 1] = __floats2half2_rn(v0, v1);
                }
            }
        }
    }
}

// ---------------- fused per-step kernel: 64 blocks x 512 threads -----------
// Per block (= batch b): scores + softmax + (alpha @ encW + giemb) + GRU.
__global__ __launch_bounds__(512) void fused_step(
    int t, const float* __restrict__ w_full, const float* __restrict__ b_full,
    const float* __restrict__ b_hh)
{
    const int b = blockIdx.x;
    const int tid = threadIdx.x;
    const int lane = tid & 31, warp = tid >> 5;   // 16 warps
    __shared__ __align__(16) float satt2[ATTD];
    __shared__ __align__(16) float sw[ATTD];
    __shared__ __align__(16) float se[PIX];
    __shared__ __align__(16) float sgi[GATE_N];
    __shared__ float sred[20];

    satt2[tid] = g_ghatt2[b * CATN + GATE_N + tid];  // att2 incl b_dec
    sw[tid] = w_full[tid];
    __syncthreads();

    // preload this lane's att2/w fragments to registers (cols fixed over p)
    const float2* satt2v = (const float2*)satt2;
    const float2* swv = (const float2*)sw;
    float2 t2r[2][4], wr[2][4];
#pragma unroll
    for (int i = 0; i < 2; i++)
#pragma unroll
        for (int j = 0; j < 4; j++) {
            int idx = (lane + 32 * i) * 4 + j;
            t2r[i][j] = satt2v[idx];
            wr[i][j] = swv[idx];
        }

    const float bf = b_full[0];
    // ---- scores: warp per pixel ----
    for (int p = warp; p < PIX; p += 16) {
        const float4* ar4 = (const float4*)(g_att1h + ((size_t)b * PIX + p) * ATTD);
        float s = 0.f;
#pragma unroll
        for (int i = 0; i < 2; i++) {
            float4 q = ar4[lane + 32 * i];
            const __half2* hh = (const __half2*)&q;
#pragma unroll
            for (int j = 0; j < 4; j++) {
                float2 x = __half22float2(hh[j]);
                s += tanh_fast(x.x + t2r[i][j].x) * wr[i][j].x
                   + tanh_fast(x.y + t2r[i][j].y) * wr[i][j].y;
            }
        }
#pragma unroll
        for (int o = 16; o; o >>= 1) s += __shfl_xor_sync(0xffffffffu, s, o);
        if (lane == 0) se[p] = s + bf;
    }
    __syncthreads();

    // ---- softmax over 196 (store raw exp; scale later) ----
    float m = -3.4e38f;
    for (int i = tid; i < PIX; i += 512) m = fmaxf(m, se[i]);
#pragma unroll
    for (int o = 16; o; o >>= 1) m = fmaxf(m, __shfl_xor_sync(0xffffffffu, m, o));
    if (lane == 0) sred[warp] = m;
    __syncthreads();
    if (warp == 0) {
        float v = (lane < 16) ? sred[lane] : -3.4e38f;
#pragma unroll
        for (int o = 16; o; o >>= 1) v = fmaxf(v, __shfl_xor_sync(0xffffffffu, v, o));
        if (lane == 0) sred[16] = v;
    }
    __syncthreads();
    const float M = sred[16];
    float s = 0.f;
    for (int i = tid; i < PIX; i += 512) {
        float ex = expf(se[i] - M);
        se[i] = ex;
        s += ex;
    }
#pragma unroll
    for (int o = 16; o; o >>= 1) s += __shfl_xor_sync(0xffffffffu, s, o);
    if (lane == 0) sred[warp] = s;
    __syncthreads();
    if (warp == 0) {
        float v = (lane < 16) ? sred[lane] : 0.f;
#pragma unroll
        for (int o = 16; o; o >>= 1) v += __shfl_xor_sync(0xffffffffu, v, o);
        if (lane == 0) sred[17] = v;
    }
    __syncthreads();
    const float inv = 1.f / sred[17];

    // ---- ctx+gi: 384 threads = 192 col-groups (8 halfs) x 2 row-halves ----
    float acc[8];
#pragma unroll
    for (int k = 0; k < 8; k++) acc[k] = 0.f;
    const int g = tid % 192;
    const int rh = tid / 192;        // 0,1 active; 2 idle
    if (rh < 2) {
        const __half* basep = g_encwh + (size_t)b * PIX * GATE_N + g * 8;
        const int r0 = rh * 98;
#pragma unroll 1
        for (int r = r0; r < r0 + 98; r += 2) {
            float4 q0 = *(const float4*)(basep + (size_t)r * GATE_N);
            float4 q1 = *(const float4*)(basep + (size_t)(r + 1) * GATE_N);
            float a0 = se[r], a1 = se[r + 1];
            const __half2* h0 = (const __half2*)&q0;
            const __half2* h1 = (const __half2*)&q1;
#pragma unroll
            for (int j = 0; j < 4; j++) {
                float2 v0 = __half22float2(h0[j]);
                float2 v1 = __half22float2(h1[j]);
                acc[2 * j]     += a0 * v0.x + a1 * v1.x;
                acc[2 * j + 1] += a0 * v0.y + a1 * v1.y;
            }
        }
    }
    if (rh == 0) {
        *(float4*)&sgi[g * 8]     = make_float4(acc[0], acc[1], acc[2], acc[3]);
        *(float4*)&sgi[g * 8 + 4] = make_float4(acc[4], acc[5], acc[6], acc[7]);
    }
    __syncthreads();
    if (rh == 1) {
        const float* ge = g_giemb + ((size_t)t * BATCH + b) * GATE_N + g * 8;
        float4 p0 = *(const float4*)&sgi[g * 8];
        float4 p1 = *(const float4*)&sgi[g * 8 + 4];
        float4 e0 = *(const float4*)ge;
        float4 e1 = *(const float4*)(ge + 4);
        float4 o0 = make_float4((acc[0] + p0.x) * inv + e0.x,
                                (acc[1] + p0.y) * inv + e0.y,
                                (acc[2] + p0.z) * inv + e0.z,
                                (acc[3] + p0.w) * inv + e0.w);
        float4 o1 = make_float4((acc[4] + p1.x) * inv + e1.x,
                                (acc[5] + p1.y) * inv + e1.y,
                                (acc[6] + p1.z) * inv + e1.z,
                                (acc[7] + p1.w) * inv + e1.w);
        *(float4*)&sgi[g * 8]     = o0;
        *(float4*)&sgi[g * 8 + 4] = o1;
    }
    __syncthreads();

    // ---- GRU: d = tid (512 = DECD) ----
    {
        const int d = tid;
        const float* gh = g_ghatt2 + (size_t)b * CATN;
        float rr = sgi[d] + gh[d] + b_hh[d];
        float zz = sgi[512 + d] + gh[512 + d] + b_hh[512 + d];
        float inp = sgi[1024 + d];
        float hnp = gh[1024 + d] + b_hh[1024 + d];
        float r = 1.f / (1.f + expf(-rr));
        float z = 1.f / (1.f + expf(-zz));
        float n = tanhf(inp + r * hnp);
        float hold = g_h[b * DECD + d];
        float hnew = (1.f - z) * n + z * hold;
        g_h[b * DECD + d] = hnew;
        g_hall[((size_t)t * BATCH + b) * DECD + d] = hnew;
    }
}

// ---------------- embedding gather -----------------------------------------
__global__ __launch_bounds__(128) void gather_embs(
    const int* __restrict__ captions, const float* __restrict__ emb_table)
{
    int r = blockIdx.x;          // t*64+b
    int t = r >> 6, b = r & 63;
    int tok = captions[b * TT + t];
    const float4* src = (const float4*)(emb_table + (size_t)tok * EMBD);
    ((float4*)(g_emball + (size_t)r * EMBD))[threadIdx.x] = src[threadIdx.x];
}

__global__ void write_caplens(const int* __restrict__ caplens, float* __restrict__ out, int n)
{
    int i = threadIdx.x;
    if (i < n && i < BATCH) out[i] = (float)(caplens[i] - 1);
}

// ---------------- host ----------------
extern "C" void kernel_launch(void* const* d_in, const int* in_sizes, int n_in,
                              void* d_out, int out_size)
{
    const float* enc       = (const float*)d_in[0];
    const int*   captions  = (const int*)  d_in[1];
    const int*   caplens   = (const int*)  d_in[2];
    const float* emb_table = (const float*)d_in[3];
    const float* W_enc     = (const float*)d_in[4];
    const float* b_enc     = (const float*)d_in[5];
    const float* W_dec     = (const float*)d_in[6];
    const float* b_dec     = (const float*)d_in[7];
    const float* w_full    = (const float*)d_in[8];
    const float* b_full    = (const float*)d_in[9];
    const float* W_ih      = (const float*)d_in[10];
    const float* b_ih      = (const float*)d_in[11];
    const float* W_hh      = (const float*)d_in[12];
    const float* b_hh      = (const float*)d_in[13];
    const float* W_fc      = (const float*)d_in[14];
    const float* b_fc      = (const float*)d_in[15];
    float* out = (float*)d_out;

    void *att1hp, *encwhp;
    float *hp, *hallp, *emballp, *giembp, *whhcatp, *biascatp, *zbp, *ghatt2p;
    cudaGetSymbolAddress(&att1hp, g_att1h);
    cudaGetSymbolAddress(&encwhp, g_encwh);
    cudaGetSymbolAddress((void**)&hp, g_h);
    cudaGetSymbolAddress((void**)&hallp, g_hall);
    cudaGetSymbolAddress((void**)&emballp, g_emball);
    cudaGetSymbolAddress((void**)&giembp, g_giemb);
    cudaGetSymbolAddress((void**)&whhcatp, g_whhcat);
    cudaGetSymbolAddress((void**)&biascatp, g_biascat);
    cudaGetSymbolAddress((void**)&zbp, g_zbias);
    cudaGetSymbolAddress((void**)&ghatt2p, g_ghatt2);

    // h0 = 0; zero bias for encW
    zerok<<<(BATCH * DECD + 255) / 256, 256>>>(hp, BATCH * DECD);
    zerok<<<(GATE_N + 255) / 256, 256>>>(zbp, GATE_N);

    // one-time prep
    gather_embs<<<MROWS, 128>>>(captions, emb_table);
    prep_cat<<<(CATN * DECD + 255) / 256, 256>>>(W_hh, W_dec, b_dec);

    // att1 (fp16) = enc @ W_enc^T + b_enc
    gemm_tf32<2><<<dim3(98, 8), 256>>>(enc, ENCD, W_enc, ENCD, b_enc, att1hp,
                                       BATCH * PIX, ATTD, ENCD);

    // encW (fp16) = enc @ W_ih[:,512:2560]^T
    gemm_tf32<2><<<dim3(98, 24), 256>>>(enc, ENCD, W_ih + 512, 2560, zbp, encwhp,
                                        BATCH * PIX, GATE_N, ENCD);

    // gi_emb = embs @ W_ih[:, :512]^T + b_ih
    gemm_tf32<0><<<dim3(16, 24), 256>>>(emballp, EMBD, W_ih, 2560,
                                        b_ih, giembp, MROWS, GATE_N, EMBD);

    for (int t = 0; t < NSTEP; t++) {
        // [gh | att2] = h @ [W_hh; W_dec]^T + [0; b_dec]
        gemm_tf32<0><<<dim3(1, 32), 256>>>(hp, DECD, whhcatp, DECD,
                                           biascatp, ghatt2p, BATCH, CATN, DECD);
        fused_step<<<BATCH, 512>>>(t, w_full, b_full, b_hh);
    }

    // logits = h_all @ W_fc^T + b_fc, stored as [b, t, v]
    gemm_tf32<1><<<dim3(16, 469), 256>>>(hallp, DECD, W_fc, DECD, b_fc, out,
                                         MROWS, VOC, DECD);

    long long NLOG = (long long)BATCH * NSTEP * VOC;
    if ((long long)out_size > NLOG) {
        int rem = (int)((long long)out_size - NLOG);
        write_caplens<<<1, 64>>>(caplens, out + NLOG, rem);
    }
}